// round 6
// baseline (speedup 1.0000x reference)
#include <cuda_runtime.h>
#include <cstdint>

#define KB    8192           // bins (bin = S>>1, S = round(v*2^14))
#define NPART 4              // histogram CTAs per batch
#define HW    262144         // H*W per batch
#define MAXB  64
#define TPB   1024

// scratch (allocation-free rule: __device__ globals; zero-initialized)
__device__ unsigned int       g_part[MAXB * NPART * KB];  // 8 MB packed partials
__device__ int                g_arrive[MAXB];             // per-batch arrival counters
__device__ int                g_done;                     // finished-batch counter
__device__ unsigned long long g_accum;                    // exact integer total

// packed word: T = d*2^22 + S,  S = sum(+-round(v*2^14)) clamped to [0,16383]
__device__ __forceinline__ int decD(unsigned int t) {
    return ((int)t + (1 << 21)) >> 22;
}
__device__ __forceinline__ unsigned int quantS(float v) {
    int S = __float2int_rn(v * 16384.0f);
    return (unsigned int)min(S, 16383);
}

// ---------------------------------------------------------------------------
// Fused kernel: histogram partials + last-CTA-per-batch scan + last-batch
// final write. grid = NPART*B, block = 1024.
// ---------------------------------------------------------------------------
__global__ void __launch_bounds__(TPB, 2) k_fused(const float* __restrict__ x,
                                                  const float* __restrict__ y,
                                                  float* __restrict__ out, int B) {
    __shared__ unsigned int sh[KB];
    __shared__ int s_last;
    __shared__ int wt[32];
    __shared__ long long wr[32];

    int cta = blockIdx.x;
    int b = cta >> 2, q = cta & 3;
    int t = threadIdx.x, lane = t & 31, wid = t >> 5;

    uint4* s4 = (uint4*)sh;
    for (int i = t; i < KB / 4; i += TPB) s4[i] = make_uint4(0u, 0u, 0u, 0u);
    __syncthreads();

    // ---- phase 1: packed signed histogram over this CTA's quarter ----
    const int QE = HW / NPART;  // 65536 elements each of x, y
    const float4* px = (const float4*)(x + (size_t)b * HW + (size_t)q * QE);
    const float4* py = (const float4*)(y + (size_t)b * HW + (size_t)q * QE);
    for (int i = t; i < QE / 4; i += TPB) {
        float4 vx = px[i];
        float4 vy = py[i];
        unsigned int s;
        s = quantS(vx.x); atomicAdd(&sh[s >> 1], (1u << 22) + s);
        s = quantS(vy.x); atomicAdd(&sh[s >> 1], (unsigned int)(-(int)((1u << 22) + s)));
        s = quantS(vx.y); atomicAdd(&sh[s >> 1], (1u << 22) + s);
        s = quantS(vy.y); atomicAdd(&sh[s >> 1], (unsigned int)(-(int)((1u << 22) + s)));
        s = quantS(vx.z); atomicAdd(&sh[s >> 1], (1u << 22) + s);
        s = quantS(vy.z); atomicAdd(&sh[s >> 1], (unsigned int)(-(int)((1u << 22) + s)));
        s = quantS(vx.w); atomicAdd(&sh[s >> 1], (1u << 22) + s);
        s = quantS(vy.w); atomicAdd(&sh[s >> 1], (unsigned int)(-(int)((1u << 22) + s)));
    }
    __syncthreads();

    // ---- write partials (coalesced uint4) ----
    unsigned int* g = g_part + (size_t)cta * KB;
    {
        uint4* g4 = (uint4*)g;
        g4[t] = s4[t];
        g4[t + TPB] = s4[t + TPB];
    }
    __threadfence();

    // ---- arrival: last CTA of this batch becomes the scanner ----
    if (t == 0) {
        int r = atomicAdd(&g_arrive[b], 1);
        s_last = (r == NPART - 1);
        if (s_last) g_arrive[b] = 0;  // reset for next graph replay
    }
    __syncthreads();
    if (!s_last) return;

    // ---- phase 2: scan this batch's 8192 combined bins (8 per thread) ----
    const unsigned int* base = g_part + (size_t)b * NPART * KB;
    int g0 = t * 8;
    int d[8], S[8];
    {
        uint4 a0 = *(const uint4*)(base + g0);
        uint4 a1 = *(const uint4*)(base + g0 + 4);
        uint4 b0 = *(const uint4*)(base + KB + g0);
        uint4 b1 = *(const uint4*)(base + KB + g0 + 4);
        uint4 c0 = *(const uint4*)(base + 2 * KB + g0);
        uint4 c1 = *(const uint4*)(base + 2 * KB + g0 + 4);
        uint4 e0 = *(const uint4*)(base + 3 * KB + g0);
        uint4 e1 = *(const uint4*)(base + 3 * KB + g0 + 4);
        unsigned int T[8];
        T[0] = a0.x + b0.x + c0.x + e0.x;
        T[1] = a0.y + b0.y + c0.y + e0.y;
        T[2] = a0.z + b0.z + c0.z + e0.z;
        T[3] = a0.w + b0.w + c0.w + e0.w;
        T[4] = a1.x + b1.x + c1.x + e1.x;
        T[5] = a1.y + b1.y + c1.y + e1.y;
        T[6] = a1.z + b1.z + c1.z + e1.z;
        T[7] = a1.w + b1.w + c1.w + e1.w;
#pragma unroll
        for (int j = 0; j < 8; ++j) {
            d[j] = decD(T[j]);
            S[j] = (int)T[j] - (d[j] << 22);
        }
    }
    int tsum = 0;
#pragma unroll
    for (int j = 0; j < 8; ++j) tsum += d[j];

    // block exclusive scan of tsum over 1024 threads
    int s = tsum;
#pragma unroll
    for (int o = 1; o < 32; o <<= 1) {
        int u = __shfl_up_sync(0xffffffffu, s, o);
        if (lane >= o) s += u;
    }
    if (lane == 31) wt[wid] = s;
    __syncthreads();
    if (wid == 0) {
        int w = wt[lane];
#pragma unroll
        for (int o = 1; o < 32; o <<= 1) {
            int u = __shfl_up_sync(0xffffffffu, w, o);
            if (lane >= o) w += u;
        }
        wt[lane] = w;
    }
    __syncthreads();
    long long Din = (long long)(wid ? wt[wid - 1] : 0) + (s - tsum);

    // exact per-bin integral: 2^15 * integ_k = 4*Din + d_k*(4k+3) - 2*S_k
    long long acc = 0;
#pragma unroll
    for (int j = 0; j < 8; ++j) {
        long long v = 4 * Din + (long long)d[j] * (4LL * (g0 + j) + 3) - 2LL * S[j];
        acc += v < 0 ? -v : v;
        Din += d[j];
    }

    // block reduce acc (int64)
#pragma unroll
    for (int o = 16; o; o >>= 1) acc += __shfl_down_sync(0xffffffffu, acc, o);
    if (lane == 0) wr[wid] = acc;
    __syncthreads();
    if (wid == 0) {
        acc = wr[lane];
#pragma unroll
        for (int o = 16; o; o >>= 1) acc += __shfl_down_sync(0xffffffffu, acc, o);
        if (lane == 0) {
            atomicAdd(&g_accum, (unsigned long long)acc);
            __threadfence();
            int r2 = atomicAdd(&g_done, 1);
            if (r2 == B - 1) {
                unsigned long long tot = atomicAdd(&g_accum, 0ull);
                out[0] = (float)((double)(long long)tot * (1.0 / 32768.0));
                g_accum = 0ull;  // reset for next graph replay
                g_done = 0;
            }
        }
    }
}

extern "C" void kernel_launch(void* const* d_in, const int* in_sizes, int n_in,
                              void* d_out, int out_size) {
    const float* x = (const float*)d_in[0];
    const float* y = (const float*)d_in[1];
    int B = in_sizes[0] / HW;
    if (B > MAXB) B = MAXB;

    k_fused<<<NPART * B, TPB>>>(x, y, (float*)d_out, B);
}